// round 12
// baseline (speedup 1.0000x reference)
#include <cuda_runtime.h>
#include <cstdint>
#include <cstdio>

// ---------------- problem constants ----------------
#define BATCH    1024
#define PPTS     128
#define NSAMP    131072        // BATCH * PPTS
#define NNET     8
#define HID      128
#define INF      66            // 3 + 60 + 3
#define LFREQ    10

// ---------------- device scratch (no allocation allowed) ----------------
__device__ float g_scalar[PPTS];
__device__ float g_X[(size_t)INF * NSAMP];          // feature-major  X[f][t]
__device__ float g_evals[(size_t)NNET * NSAMP * 4]; // evals[n][t][4]

// ---------------- packed f32x2 helpers ----------------
__device__ __forceinline__ void ffma2(unsigned long long& d,
                                      unsigned long long a,
                                      unsigned long long b) {
    asm("fma.rn.f32x2 %0, %1, %2, %0;" : "+l"(d) : "l"(a), "l"(b));
}
__device__ __forceinline__ unsigned long long pack2(float lo, float hi) {
    unsigned long long r;
    asm("mov.b64 %0, {%1, %2};" : "=l"(r) : "f"(lo), "f"(hi));
    return r;
}
__device__ __forceinline__ void unpack2(unsigned long long v, float& lo, float& hi) {
    asm("mov.b64 {%0, %1}, %2;" : "=f"(lo), "=f"(hi) : "l"(v));
}

// ---------------- threefry2x32, JAX partitionable path, key(42) ----------------
// Per element p: counter64 = p -> (x0 = hi = 0, x1 = lo = p); run threefry2x32;
// for bit_width 32 the two output words are XOR-folded: bits = out0 ^ out1.
// (Variants if this fails at rel_err O(1): truncation bits=out1; or paired
//  counter=p>>1 with word selected by p&1.)
__device__ __forceinline__ uint32_t rotl32(uint32_t x, int r) {
    return (x << r) | (x >> (32 - r));
}

__global__ void k_scalar(const float* __restrict__ ssp, const float* __restrict__ sep) {
    int p = threadIdx.x;              // 0..127
    if (p >= PPTS) return;
    const uint32_t k0 = 0u, k1 = 42u;
    const uint32_t kx = k0 ^ k1 ^ 0x1BD11BDAu;
    uint32_t ks[3] = {k0, k1, kx};
    uint32_t x0 = 0u + k0;            // counter high word = 0
    uint32_t x1 = (uint32_t)p + k1;   // counter low word  = p
    const int RA[4] = {13, 15, 26, 6};
    const int RB[4] = {17, 29, 16, 24};
    #pragma unroll
    for (int g = 0; g < 5; g++) {
        #pragma unroll
        for (int j = 0; j < 4; j++) {
            int r = (g & 1) ? RB[j] : RA[j];
            x0 += x1;
            x1 = rotl32(x1, r);
            x1 ^= x0;
        }
        x0 += ks[(g + 1) % 3];
        x1 += ks[(g + 2) % 3] + (uint32_t)(g + 1);
    }
    uint32_t bits = x0 ^ x1;          // XOR fold (partitionable, bit_width<64)
    float sstart = *ssp, send = *sep;
    float step = (send - sstart) / (float)(PPTS - 1);
    float u = __uint_as_float((bits >> 9) | 0x3F800000u) - 1.0f;
    u = fmaxf(0.0f, u);
    float off = (u * (send - sstart)) / (float)(PPTS - 1);
    g_scalar[p] = (sstart + (float)p * step) + off;
}

// ---------------- positional encoding into feature-major X ----------------
__global__ void k_feat(const float* __restrict__ ro, const float* __restrict__ rd) {
    int t = blockIdx.x * blockDim.x + threadIdx.x;
    if (t >= NSAMP) return;
    int b = t >> 7;
    int p = t & 127;
    float s = g_scalar[p];
    float dx = rd[b * 3 + 0], dy = rd[b * 3 + 1], dz = rd[b * 3 + 2];
    float px = dx * s + ro[b * 3 + 0];
    float py = dy * s + ro[b * 3 + 1];
    float pz = dz * s + ro[b * 3 + 2];
    g_X[(size_t)0 * NSAMP + t] = px;
    g_X[(size_t)1 * NSAMP + t] = py;
    g_X[(size_t)2 * NSAMP + t] = pz;
    float freq = 3.14159265358979323846f;   // rounds to f32(pi), matches jnp
    #pragma unroll
    for (int l = 0; l < LFREQ; l++) {
        float cx, sx, cy, sy, cz, sz;
        sincosf(px * freq, &sx, &cx);
        sincosf(py * freq, &sy, &cy);
        sincosf(pz * freq, &sz, &cz);
        size_t base = (size_t)(3 + l * 6) * NSAMP + t;
        g_X[base + (size_t)0 * NSAMP] = cx;
        g_X[base + (size_t)1 * NSAMP] = cy;
        g_X[base + (size_t)2 * NSAMP] = cz;
        g_X[base + (size_t)3 * NSAMP] = sx;
        g_X[base + (size_t)4 * NSAMP] = sy;
        g_X[base + (size_t)5 * NSAMP] = sz;
        freq *= 2.0f;
    }
    g_X[(size_t)63 * NSAMP + t] = dx;
    g_X[(size_t)64 * NSAMP + t] = dy;
    g_X[(size_t)65 * NSAMP + t] = dz;
}

// ---------------- fused 3-layer MLP per (128-sample tile, net) ----------------
// smem (floats): sX 66*128 | sW 128*128 | sHT 128*133 | sB1 128 | sB2 128 | sW3 512 | sB3 4
#define SM_X   0
#define SM_W   (SM_X + INF * 128)            // 8448
#define SM_HT  (SM_W + HID * HID)            // +16384
#define HT_STR 133
#define SM_B1  (SM_HT + HID * HT_STR)        // +17024
#define SM_B2  (SM_B1 + HID)
#define SM_W3  (SM_B2 + HID)
#define SM_B3  (SM_W3 + HID * 4)
#define SMEM_FLOATS (SM_B3 + 4)
#define SMEM_BYTES  (SMEM_FLOATS * 4)

__global__ void __launch_bounds__(256)
k_mlp(const float* __restrict__ W1, const float* __restrict__ b1,
      const float* __restrict__ W2, const float* __restrict__ b2,
      const float* __restrict__ W3, const float* __restrict__ b3) {
    extern __shared__ float sm[];
    float* sX  = sm + SM_X;
    float* sW  = sm + SM_W;
    float* sHT = sm + SM_HT;
    float* sB1 = sm + SM_B1;
    float* sB2 = sm + SM_B2;
    float* sW3 = sm + SM_W3;
    float* sB3 = sm + SM_B3;

    const int tile = blockIdx.x;   // 0..1023 -> samples tile*128 ..
    const int n    = blockIdx.y;   // network
    const int tid  = threadIdx.x;
    const int tx   = tid & 15;     // 0..15 -> hid cols tx*8..
    const int ty   = tid >> 4;     // 0..15 -> samples ty*8..
    const int t0   = tile * 128;

    // ---- stage X tile (feature-major) + W1 + biases + W3 ----
    for (int idx = tid; idx < INF * 128; idx += 256) {
        int f = idx >> 7, s = idx & 127;
        sX[idx] = g_X[(size_t)f * NSAMP + t0 + s];
    }
    {
        const float4* wp = (const float4*)(W1 + (size_t)n * INF * HID);
        float4* sWv = (float4*)sW;
        for (int idx = tid; idx < (INF * HID) / 4; idx += 256) sWv[idx] = wp[idx];
    }
    if (tid < HID) {
        sB1[tid] = b1[n * HID + tid];
        sB2[tid] = b2[n * HID + tid];
    }
    // FIX (R10 post-mortem): previous code wrote only sW3[0..255] (256 threads,
    // guard tid < 512) leaving sW3[256..511] = garbage shared memory. Strided
    // loop now stages all 512 entries of W3[n].
    for (int idx = tid; idx < HID * 4; idx += 256)
        sW3[idx] = W3[(size_t)n * HID * 4 + idx];
    if (tid < 4) sB3[tid] = b3[n * 4 + tid];
    __syncthreads();

    union F4 { float4 v; float f[4]; unsigned long long p[2]; };

    // ---- GEMM1: h1[s][h] = relu(X @ W1 + b1) ----
    unsigned long long acc[4][8];
    #pragma unroll
    for (int i = 0; i < 4; i++)
        #pragma unroll
        for (int j = 0; j < 8; j++) acc[i][j] = 0ull;

    #pragma unroll 2
    for (int f = 0; f < INF; f++) {
        F4 xa, xb, wa, wb;
        xa.v = *(const float4*)&sX[f * 128 + ty * 8];
        xb.v = *(const float4*)&sX[f * 128 + ty * 8 + 4];
        wa.v = *(const float4*)&sW[f * 128 + tx * 8];
        wb.v = *(const float4*)&sW[f * 128 + tx * 8 + 4];
        unsigned long long wp[8];
        #pragma unroll
        for (int j = 0; j < 8; j++) {
            float w = (j < 4) ? wa.f[j] : wb.f[j - 4];
            wp[j] = pack2(w, w);
        }
        #pragma unroll
        for (int j = 0; j < 8; j++) {
            ffma2(acc[0][j], xa.p[0], wp[j]);
            ffma2(acc[1][j], xa.p[1], wp[j]);
            ffma2(acc[2][j], xb.p[0], wp[j]);
            ffma2(acc[3][j], xb.p[1], wp[j]);
        }
    }
    __syncthreads();   // all GEMM1 reads of sX/sW done

    // bias + relu, write transposed h1 -> sHT[h][s]  (reads sB1, untouched later)
    #pragma unroll
    for (int j = 0; j < 8; j++) {
        float bj = sB1[tx * 8 + j];
        #pragma unroll
        for (int i2 = 0; i2 < 4; i2++) {
            float lo, hi;
            unpack2(acc[i2][j], lo, hi);
            lo = fmaxf(lo + bj, 0.0f);
            hi = fmaxf(hi + bj, 0.0f);
            sHT[(tx * 8 + j) * HT_STR + ty * 8 + 2 * i2]     = lo;
            sHT[(tx * 8 + j) * HT_STR + ty * 8 + 2 * i2 + 1] = hi;
        }
    }
    // stage W2 (overwrites sW; GEMM1 reads of sW completed before prior sync)
    {
        const float4* wp = (const float4*)(W2 + (size_t)n * HID * HID);
        float4* sWv = (float4*)sW;
        for (int idx = tid; idx < (HID * HID) / 4; idx += 256) sWv[idx] = wp[idx];
    }
    __syncthreads();

    // ---- GEMM2: h2[s][k] = relu(h1 @ W2 + b2) ----
    #pragma unroll
    for (int i = 0; i < 4; i++)
        #pragma unroll
        for (int j = 0; j < 8; j++) acc[i][j] = 0ull;

    #pragma unroll 2
    for (int k = 0; k < HID; k++) {
        float xv[8];
        #pragma unroll
        for (int i = 0; i < 8; i++) xv[i] = sHT[k * HT_STR + ty * 8 + i];
        unsigned long long xp[4];
        #pragma unroll
        for (int i2 = 0; i2 < 4; i2++) xp[i2] = pack2(xv[2 * i2], xv[2 * i2 + 1]);
        F4 wa, wb;
        wa.v = *(const float4*)&sW[k * 128 + tx * 8];
        wb.v = *(const float4*)&sW[k * 128 + tx * 8 + 4];
        unsigned long long wp[8];
        #pragma unroll
        for (int j = 0; j < 8; j++) {
            float w = (j < 4) ? wa.f[j] : wb.f[j - 4];
            wp[j] = pack2(w, w);
        }
        #pragma unroll
        for (int j = 0; j < 8; j++) {
            ffma2(acc[0][j], xp[0], wp[j]);
            ffma2(acc[1][j], xp[1], wp[j]);
            ffma2(acc[2][j], xp[2], wp[j]);
            ffma2(acc[3][j], xp[3], wp[j]);
        }
    }
    __syncthreads();   // all GEMM2 reads of sHT done before overwrite

    #pragma unroll
    for (int j = 0; j < 8; j++) {
        float bj = sB2[tx * 8 + j];
        #pragma unroll
        for (int i2 = 0; i2 < 4; i2++) {
            float lo, hi;
            unpack2(acc[i2][j], lo, hi);
            lo = fmaxf(lo + bj, 0.0f);
            hi = fmaxf(hi + bj, 0.0f);
            sHT[(tx * 8 + j) * HT_STR + ty * 8 + 2 * i2]     = lo;
            sHT[(tx * 8 + j) * HT_STR + ty * 8 + 2 * i2 + 1] = hi;
        }
    }
    __syncthreads();

    // ---- layer3: ev[s][o] = h2 @ W3 + b3 ----
    if (tid < 128) {
        float a0 = sB3[0], a1 = sB3[1], a2 = sB3[2], a3 = sB3[3];
        #pragma unroll 4
        for (int k = 0; k < HID; k++) {
            float v = sHT[k * HT_STR + tid];
            a0 += v * sW3[k * 4 + 0];
            a1 += v * sW3[k * 4 + 1];
            a2 += v * sW3[k * 4 + 2];
            a3 += v * sW3[k * 4 + 3];
        }
        float4 r = make_float4(a0, a1, a2, a3);
        *(float4*)&g_evals[((size_t)n * NSAMP + t0 + tid) * 4] = r;
    }
}

// ---------------- mixture + volume rendering + splits output ----------------
__global__ void __launch_bounds__(128)
k_render(const float* __restrict__ ro, const float* __restrict__ rd,
         const float* __restrict__ Ws, const float* __restrict__ bs,
         float* __restrict__ out) {
    int b = blockIdx.x;
    int p = threadIdx.x;
    int t = b * PPTS + p;

    float dx = rd[b * 3 + 0], dy = rd[b * 3 + 1], dz = rd[b * 3 + 2];
    float s  = g_scalar[p];
    float px = dx * s + ro[b * 3 + 0];
    float py = dy * s + ro[b * 3 + 1];
    float pz = dz * s + ro[b * 3 + 2];

    // splits = softmax(pos @ Ws + bs)
    float lo_[NNET];
    float m = -1e30f;
    #pragma unroll
    for (int n = 0; n < NNET; n++) {
        float l = px * Ws[0 * NNET + n] + py * Ws[1 * NNET + n] + pz * Ws[2 * NNET + n] + bs[n];
        lo_[n] = l;
        m = fmaxf(m, l);
    }
    float denom = 0.0f;
    #pragma unroll
    for (int n = 0; n < NNET; n++) { lo_[n] = expf(lo_[n] - m); denom += lo_[n]; }
    float inv = 1.0f / denom;
    float* spl = out + BATCH * 3;
    float nv0 = 0.f, nv1 = 0.f, nv2 = 0.f, nv3 = 0.f;
    #pragma unroll
    for (int n = 0; n < NNET; n++) {
        float spn = lo_[n] * inv;
        spl[(size_t)t * NNET + n] = spn;
        float4 ev = *(const float4*)&g_evals[((size_t)n * NSAMP + t) * 4];
        nv0 += spn * ev.x;
        nv1 += spn * ev.y;
        nv2 += spn * ev.z;
        nv3 += spn * ev.w;
    }

    // sd, inclusive cumsum, weights
    float sdv = 0.0f;
    if (p < PPTS - 1) sdv = nv3 * (g_scalar[p + 1] - g_scalar[p]);

    __shared__ float sc[PPTS];
    sc[p] = sdv;
    __syncthreads();
    #pragma unroll
    for (int off = 1; off < PPTS; off <<= 1) {
        float add = (p >= off) ? sc[p - off] : 0.0f;
        __syncthreads();
        sc[p] += add;
        __syncthreads();
    }
    float csum = sc[p];
    float w = (p < PPTS - 1) ? expf(csum) * (1.0f - expf(-sdv)) : 0.0f;

    float rc[3] = {w * nv0, w * nv1, w * nv2};
    #pragma unroll
    for (int c = 0; c < 3; c++) {
        __syncthreads();
        sc[p] = rc[c];
        __syncthreads();
        for (int off = 64; off > 0; off >>= 1) {
            if (p < off) sc[p] += sc[p + off];
            __syncthreads();
        }
        if (p == 0) out[b * 3 + c] = sc[0];
    }
}

// ---------------- launch ----------------
extern "C" void kernel_launch(void* const* d_in, const int* in_sizes, int n_in,
                              void* d_out, int out_size) {
    // Diagnostic (host-side, graph-capture-safe, deterministic): surfaces the
    // actual input layout in the bench log.
    fprintf(stderr, "[kdiag] n_in=%d out_size=%d sizes:", n_in, out_size);
    for (int i = 0; i < n_in; i++) fprintf(stderr, " %d", in_sizes[i]);
    fprintf(stderr, "\n");

    const float* ro = (const float*)d_in[0];
    const float* rd = (const float*)d_in[1];
    const float* ss = (const float*)d_in[2];
    const float* se = (const float*)d_in[3];

    // Anchor the weight block by W1's unique element count (8*66*128 = 67584):
    // robust to whether num_integration_points appears as a device input.
    int iW1 = -1;
    for (int i = 0; i < n_in; i++) {
        if (in_sizes[i] == NNET * INF * HID) { iW1 = i; break; }
    }
    if (iW1 < 0) iW1 = 5;   // fallback to nominal layout
    const float* W1 = (const float*)d_in[iW1 + 0];
    const float* b1 = (const float*)d_in[iW1 + 1];
    const float* W2 = (const float*)d_in[iW1 + 2];
    const float* b2 = (const float*)d_in[iW1 + 3];
    const float* W3 = (const float*)d_in[iW1 + 4];
    const float* b3 = (const float*)d_in[iW1 + 5];
    const float* Ws = (const float*)d_in[iW1 + 6];
    const float* bs = (const float*)d_in[iW1 + 7];
    float* out = (float*)d_out;

    cudaFuncSetAttribute(k_mlp, cudaFuncAttributeMaxDynamicSharedMemorySize, SMEM_BYTES);

    k_scalar<<<1, PPTS>>>(ss, se);
    k_feat<<<NSAMP / 256, 256>>>(ro, rd);
    k_mlp<<<dim3(BATCH, NNET), 256, SMEM_BYTES>>>(W1, b1, W2, b2, W3, b3);
    k_render<<<BATCH, PPTS>>>(ro, rd, Ws, bs, out);
}

// round 13
// speedup vs baseline: 1.1408x; 1.1408x over previous
#include <cuda_runtime.h>
#include <cstdint>
#include <cstdio>

// ---------------- problem constants ----------------
#define BATCH    1024
#define PPTS     128
#define NSAMP    131072        // BATCH * PPTS
#define NNET     8
#define HID      128
#define INF      66            // 3 + 60 + 3
#define LFREQ    10

// ---------------- device scratch (no allocation allowed) ----------------
__device__ float g_scalar[PPTS];
__device__ float g_X[(size_t)INF * NSAMP];          // feature-major  X[f][t]
__device__ float g_evals[(size_t)NNET * NSAMP * 4]; // evals[n][t][4]

// ---------------- packed f32x2 helpers ----------------
__device__ __forceinline__ void ffma2(unsigned long long& d,
                                      unsigned long long a,
                                      unsigned long long b) {
    asm("fma.rn.f32x2 %0, %1, %2, %0;" : "+l"(d) : "l"(a), "l"(b));
}
__device__ __forceinline__ unsigned long long pack2(float lo, float hi) {
    unsigned long long r;
    asm("mov.b64 %0, {%1, %2};" : "=l"(r) : "f"(lo), "f"(hi));
    return r;
}
__device__ __forceinline__ void unpack2(unsigned long long v, float& lo, float& hi) {
    asm("mov.b64 {%0, %1}, %2;" : "=f"(lo), "=f"(hi) : "l"(v));
}

// ---------------- threefry2x32, JAX partitionable path, key(42) ----------------
// counter64 = p -> (x0=0, x1=p); XOR-fold outputs (verified by R12 pass).
__device__ __forceinline__ uint32_t rotl32(uint32_t x, int r) {
    return (x << r) | (x >> (32 - r));
}

__global__ void k_scalar(const float* __restrict__ ssp, const float* __restrict__ sep) {
    int p = threadIdx.x;
    if (p >= PPTS) return;
    const uint32_t k0 = 0u, k1 = 42u;
    const uint32_t kx = k0 ^ k1 ^ 0x1BD11BDAu;
    uint32_t ks[3] = {k0, k1, kx};
    uint32_t x0 = 0u + k0;
    uint32_t x1 = (uint32_t)p + k1;
    const int RA[4] = {13, 15, 26, 6};
    const int RB[4] = {17, 29, 16, 24};
    #pragma unroll
    for (int g = 0; g < 5; g++) {
        #pragma unroll
        for (int j = 0; j < 4; j++) {
            int r = (g & 1) ? RB[j] : RA[j];
            x0 += x1;
            x1 = rotl32(x1, r);
            x1 ^= x0;
        }
        x0 += ks[(g + 1) % 3];
        x1 += ks[(g + 2) % 3] + (uint32_t)(g + 1);
    }
    uint32_t bits = x0 ^ x1;
    float sstart = *ssp, send = *sep;
    float step = (send - sstart) / (float)(PPTS - 1);
    float u = __uint_as_float((bits >> 9) | 0x3F800000u) - 1.0f;
    u = fmaxf(0.0f, u);
    float off = (u * (send - sstart)) / (float)(PPTS - 1);
    g_scalar[p] = (sstart + (float)p * step) + off;
}

// ---------------- positional encoding into feature-major X ----------------
__global__ void k_feat(const float* __restrict__ ro, const float* __restrict__ rd) {
    int t = blockIdx.x * blockDim.x + threadIdx.x;
    if (t >= NSAMP) return;
    int b = t >> 7;
    int p = t & 127;
    float s = g_scalar[p];
    float dx = rd[b * 3 + 0], dy = rd[b * 3 + 1], dz = rd[b * 3 + 2];
    float px = dx * s + ro[b * 3 + 0];
    float py = dy * s + ro[b * 3 + 1];
    float pz = dz * s + ro[b * 3 + 2];
    g_X[(size_t)0 * NSAMP + t] = px;
    g_X[(size_t)1 * NSAMP + t] = py;
    g_X[(size_t)2 * NSAMP + t] = pz;
    float freq = 3.14159265358979323846f;
    #pragma unroll
    for (int l = 0; l < LFREQ; l++) {
        float cx, sx, cy, sy, cz, sz;
        sincosf(px * freq, &sx, &cx);
        sincosf(py * freq, &sy, &cy);
        sincosf(pz * freq, &sz, &cz);
        size_t base = (size_t)(3 + l * 6) * NSAMP + t;
        g_X[base + (size_t)0 * NSAMP] = cx;
        g_X[base + (size_t)1 * NSAMP] = cy;
        g_X[base + (size_t)2 * NSAMP] = cz;
        g_X[base + (size_t)3 * NSAMP] = sx;
        g_X[base + (size_t)4 * NSAMP] = sy;
        g_X[base + (size_t)5 * NSAMP] = sz;
        freq *= 2.0f;
    }
    g_X[(size_t)63 * NSAMP + t] = dx;
    g_X[(size_t)64 * NSAMP + t] = dy;
    g_X[(size_t)65 * NSAMP + t] = dz;
}

// ---------------- fused MLP v2: 512 threads, broadcast-x mapping ----------------
// smem (floats): sW 16384 | sHT 16896 (X stage first, then h1/h2 swizzled) |
//                sB1 128 | sB2 128 | sW3 512 | sB3 4   -> 34052 floats = 136208 B
#define SMF_W   0
#define SMF_HT  16384
#define SMF_B1  (16384 + 16896)
#define SMF_B2  (SMF_B1 + 128)
#define SMF_W3  (SMF_B2 + 128)
#define SMF_B3  (SMF_W3 + 512)
#define SMEM_FLOATS (SMF_B3 + 4)
#define SMEM_BYTES  (SMEM_FLOATS * 4)
#define HT_R 132   // row stride (floats) for swizzled h buffer

// swizzled offset within a row: s in [0,128): chunk(s>>2) XOR key(k)
__device__ __forceinline__ int ht_off(int s, int key) {
    return ((((s >> 2) ^ key) << 2) | (s & 3));
}

__global__ void __launch_bounds__(512)
k_mlp(const float* __restrict__ W1, const float* __restrict__ b1,
      const float* __restrict__ W2, const float* __restrict__ b2,
      const float* __restrict__ W3, const float* __restrict__ b3) {
    extern __shared__ float sm[];
    float* sW  = sm + SMF_W;
    float* sHT = sm + SMF_HT;
    float* sB1 = sm + SMF_B1;
    float* sB2 = sm + SMF_B2;
    float* sW3 = sm + SMF_W3;
    float* sB3 = sm + SMF_B3;

    const int tile = blockIdx.x;
    const int n    = blockIdx.y;
    const int tid  = threadIdx.x;
    const int wid  = tid >> 5;        // 0..15  -> samples wid*8..+8
    const int lane = tid & 31;        // 0..31  -> cols lane*4..+4
    const int t0   = tile * 128;
    const int s8   = wid * 8;
    const int c0   = lane * 4;
    const int wkey = (lane >> 1) & 7; // write-swizzle key = (h>>3)&7 for h=c0+jj

    union F4 { float4 v; float f[4]; unsigned long long p[2]; };

    // ---- stage X tile into sHT area (feature-major, stride 128) + W1 + consts
    for (int idx = tid; idx < INF * 128; idx += 512) {
        int f = idx >> 7, s = idx & 127;
        sHT[f * 128 + s] = g_X[(size_t)f * NSAMP + t0 + s];
    }
    {
        const float4* wp = (const float4*)(W1 + (size_t)n * INF * HID);
        float4* d = (float4*)sW;
        for (int idx = tid; idx < (INF * HID) / 4; idx += 512) d[idx] = wp[idx];
    }
    if (tid < HID) { sB1[tid] = b1[n * HID + tid]; sB2[tid] = b2[n * HID + tid]; }
    for (int idx = tid; idx < HID * 4; idx += 512) sW3[idx] = W3[(size_t)n * HID * 4 + idx];
    if (tid < 4) sB3[tid] = b3[n * 4 + tid];
    __syncthreads();

    unsigned long long acc[8][2];

    // ---- GEMM1: h1[s][c] = X @ W1  (acc over f) ----
    #pragma unroll
    for (int i = 0; i < 8; i++) { acc[i][0] = 0ull; acc[i][1] = 0ull; }
    #pragma unroll 4
    for (int f = 0; f < INF; f++) {
        F4 xa, xb, wv;
        xa.v = *(const float4*)&sHT[f * 128 + s8];       // samples s8..+4 (broadcast)
        xb.v = *(const float4*)&sHT[f * 128 + s8 + 4];   // samples s8+4..+8
        wv.v = *(const float4*)&sW[f * 128 + c0];        // cols c0..+4
        unsigned long long w0 = wv.p[0], w1 = wv.p[1];
        #pragma unroll
        for (int i = 0; i < 4; i++) {
            unsigned long long xd = pack2(xa.f[i], xa.f[i]);
            ffma2(acc[i][0], xd, w0);
            ffma2(acc[i][1], xd, w1);
        }
        #pragma unroll
        for (int i = 0; i < 4; i++) {
            unsigned long long xd = pack2(xb.f[i], xb.f[i]);
            ffma2(acc[4 + i][0], xd, w0);
            ffma2(acc[4 + i][1], xd, w1);
        }
    }
    __syncthreads();   // GEMM1 done reading sW + X-in-sHT

    // ---- epilogue1: bias+relu, write h1 -> sHT swizzled [h][s], R=132 ----
    {
        float bb[4] = { sB1[c0], sB1[c0 + 1], sB1[c0 + 2], sB1[c0 + 3] };
        float v[8][4];
        #pragma unroll
        for (int i = 0; i < 8; i++) {
            unpack2(acc[i][0], v[i][0], v[i][1]);
            unpack2(acc[i][1], v[i][2], v[i][3]);
            #pragma unroll
            for (int j = 0; j < 4; j++) v[i][j] = fmaxf(v[i][j] + bb[j], 0.0f);
        }
        #pragma unroll
        for (int jj = 0; jj < 4; jj++) {
            int h = c0 + jj;
            float4 A = make_float4(v[0][jj], v[1][jj], v[2][jj], v[3][jj]);
            float4 B = make_float4(v[4][jj], v[5][jj], v[6][jj], v[7][jj]);
            *(float4*)&sHT[h * HT_R + (((wid * 2)     ^ wkey) << 2)] = A;
            *(float4*)&sHT[h * HT_R + (((wid * 2 + 1) ^ wkey) << 2)] = B;
        }
    }
    // stage W2 (overwrites sW; GEMM1 reads completed before prior sync)
    {
        const float4* wp = (const float4*)(W2 + (size_t)n * HID * HID);
        float4* d = (float4*)sW;
        for (int idx = tid; idx < (HID * HID) / 4; idx += 512) d[idx] = wp[idx];
    }
    __syncthreads();

    // ---- GEMM2: h2 = relu(h1 @ W2 + b2) ----
    #pragma unroll
    for (int i = 0; i < 8; i++) { acc[i][0] = 0ull; acc[i][1] = 0ull; }
    #pragma unroll 4
    for (int k = 0; k < HID; k++) {
        int key = (k >> 3) & 7;
        F4 xa, xb, wv;
        xa.v = *(const float4*)&sHT[k * HT_R + (((wid * 2)     ^ key) << 2)];
        xb.v = *(const float4*)&sHT[k * HT_R + (((wid * 2 + 1) ^ key) << 2)];
        wv.v = *(const float4*)&sW[k * 128 + c0];
        unsigned long long w0 = wv.p[0], w1 = wv.p[1];
        #pragma unroll
        for (int i = 0; i < 4; i++) {
            unsigned long long xd = pack2(xa.f[i], xa.f[i]);
            ffma2(acc[i][0], xd, w0);
            ffma2(acc[i][1], xd, w1);
        }
        #pragma unroll
        for (int i = 0; i < 4; i++) {
            unsigned long long xd = pack2(xb.f[i], xb.f[i]);
            ffma2(acc[4 + i][0], xd, w0);
            ffma2(acc[4 + i][1], xd, w1);
        }
    }
    __syncthreads();   // GEMM2 done reading sHT(h1)

    // ---- epilogue2: bias+relu, write h2 -> sHT swizzled ----
    {
        float bb[4] = { sB2[c0], sB2[c0 + 1], sB2[c0 + 2], sB2[c0 + 3] };
        float v[8][4];
        #pragma unroll
        for (int i = 0; i < 8; i++) {
            unpack2(acc[i][0], v[i][0], v[i][1]);
            unpack2(acc[i][1], v[i][2], v[i][3]);
            #pragma unroll
            for (int j = 0; j < 4; j++) v[i][j] = fmaxf(v[i][j] + bb[j], 0.0f);
        }
        #pragma unroll
        for (int jj = 0; jj < 4; jj++) {
            int h = c0 + jj;
            float4 A = make_float4(v[0][jj], v[1][jj], v[2][jj], v[3][jj]);
            float4 B = make_float4(v[4][jj], v[5][jj], v[6][jj], v[7][jj]);
            *(float4*)&sHT[h * HT_R + (((wid * 2)     ^ wkey) << 2)] = A;
            *(float4*)&sHT[h * HT_R + (((wid * 2 + 1) ^ wkey) << 2)] = B;
        }
    }
    __syncthreads();

    // ---- layer3: ev[s][o] = h2 @ W3 + b3  (512 threads = 128 s x 4 o) ----
    {
        int o = tid >> 7, s = tid & 127;
        float a = sB3[o];
        #pragma unroll 4
        for (int k = 0; k < HID; k++) {
            float vv = sHT[k * HT_R + ht_off(s, (k >> 3) & 7)];
            a += vv * sW3[k * 4 + o];
        }
        g_evals[((size_t)n * NSAMP + t0 + s) * 4 + o] = a;
    }
}

// ---------------- mixture + volume rendering + splits output ----------------
__global__ void __launch_bounds__(128)
k_render(const float* __restrict__ ro, const float* __restrict__ rd,
         const float* __restrict__ Ws, const float* __restrict__ bs,
         float* __restrict__ out) {
    int b = blockIdx.x;
    int p = threadIdx.x;
    int t = b * PPTS + p;

    float dx = rd[b * 3 + 0], dy = rd[b * 3 + 1], dz = rd[b * 3 + 2];
    float s  = g_scalar[p];
    float px = dx * s + ro[b * 3 + 0];
    float py = dy * s + ro[b * 3 + 1];
    float pz = dz * s + ro[b * 3 + 2];

    float lo_[NNET];
    float m = -1e30f;
    #pragma unroll
    for (int n = 0; n < NNET; n++) {
        float l = px * Ws[0 * NNET + n] + py * Ws[1 * NNET + n] + pz * Ws[2 * NNET + n] + bs[n];
        lo_[n] = l;
        m = fmaxf(m, l);
    }
    float denom = 0.0f;
    #pragma unroll
    for (int n = 0; n < NNET; n++) { lo_[n] = expf(lo_[n] - m); denom += lo_[n]; }
    float inv = 1.0f / denom;
    float* spl = out + BATCH * 3;
    float nv0 = 0.f, nv1 = 0.f, nv2 = 0.f, nv3 = 0.f;
    #pragma unroll
    for (int n = 0; n < NNET; n++) {
        float spn = lo_[n] * inv;
        spl[(size_t)t * NNET + n] = spn;
        float4 ev = *(const float4*)&g_evals[((size_t)n * NSAMP + t) * 4];
        nv0 += spn * ev.x;
        nv1 += spn * ev.y;
        nv2 += spn * ev.z;
        nv3 += spn * ev.w;
    }

    float sdv = 0.0f;
    if (p < PPTS - 1) sdv = nv3 * (g_scalar[p + 1] - g_scalar[p]);

    __shared__ float sc[PPTS];
    sc[p] = sdv;
    __syncthreads();
    #pragma unroll
    for (int off = 1; off < PPTS; off <<= 1) {
        float add = (p >= off) ? sc[p - off] : 0.0f;
        __syncthreads();
        sc[p] += add;
        __syncthreads();
    }
    float csum = sc[p];
    float w = (p < PPTS - 1) ? expf(csum) * (1.0f - expf(-sdv)) : 0.0f;

    float rc[3] = {w * nv0, w * nv1, w * nv2};
    #pragma unroll
    for (int c = 0; c < 3; c++) {
        __syncthreads();
        sc[p] = rc[c];
        __syncthreads();
        for (int off = 64; off > 0; off >>= 1) {
            if (p < off) sc[p] += sc[p + off];
            __syncthreads();
        }
        if (p == 0) out[b * 3 + c] = sc[0];
    }
}

// ---------------- launch ----------------
extern "C" void kernel_launch(void* const* d_in, const int* in_sizes, int n_in,
                              void* d_out, int out_size) {
    fprintf(stderr, "[kdiag] n_in=%d out_size=%d sizes:", n_in, out_size);
    for (int i = 0; i < n_in; i++) fprintf(stderr, " %d", in_sizes[i]);
    fprintf(stderr, "\n");

    const float* ro = (const float*)d_in[0];
    const float* rd = (const float*)d_in[1];
    const float* ss = (const float*)d_in[2];
    const float* se = (const float*)d_in[3];

    int iW1 = -1;
    for (int i = 0; i < n_in; i++) {
        if (in_sizes[i] == NNET * INF * HID) { iW1 = i; break; }
    }
    if (iW1 < 0) iW1 = 5;
    const float* W1 = (const float*)d_in[iW1 + 0];
    const float* b1 = (const float*)d_in[iW1 + 1];
    const float* W2 = (const float*)d_in[iW1 + 2];
    const float* b2 = (const float*)d_in[iW1 + 3];
    const float* W3 = (const float*)d_in[iW1 + 4];
    const float* b3 = (const float*)d_in[iW1 + 5];
    const float* Ws = (const float*)d_in[iW1 + 6];
    const float* bs = (const float*)d_in[iW1 + 7];
    float* out = (float*)d_out;

    cudaFuncSetAttribute(k_mlp, cudaFuncAttributeMaxDynamicSharedMemorySize, SMEM_BYTES);

    k_scalar<<<1, PPTS>>>(ss, se);
    k_feat<<<NSAMP / 256, 256>>>(ro, rd);
    k_mlp<<<dim3(BATCH, NNET), 512, SMEM_BYTES>>>(W1, b1, W2, b2, W3, b3);
    k_render<<<BATCH, PPTS>>>(ro, rd, Ws, bs, out);
}

// round 16
// speedup vs baseline: 1.4343x; 1.2573x over previous
#include <cuda_runtime.h>
#include <cuda_bf16.h>
#include <cstdint>
#include <cstdio>

// ---------------- problem constants ----------------
#define BATCH    1024
#define PPTS     128
#define NSAMP    131072
#define NNET     8
#define HID      128
#define INF      66
#define LFREQ    10
#define KPAD     128
#define K1PAD    80

// ---------------- device scratch ----------------
__device__ float g_scalar[PPTS];
__device__ float g_X[(size_t)NSAMP * INF];            // sample-major X[t][f]
__device__ float g_evals[(size_t)NNET * NSAMP * 4];
// pre-split transposed weights, row-major [h][KPAD] bf16 (built by k_prep)
__device__ __nv_bfloat16 g_B1hi[NNET][HID * KPAD], g_B1lo[NNET][HID * KPAD];
__device__ __nv_bfloat16 g_B2hi[NNET][HID * KPAD], g_B2lo[NNET][HID * KPAD];

// ---------------- helpers ----------------
__device__ __forceinline__ uint32_t smem_u32(const void* p) {
    uint32_t a;
    asm("{ .reg .u64 t; cvta.to.shared.u64 t, %1; cvt.u32.u64 %0, t; }" : "=r"(a) : "l"(p));
    return a;
}
__device__ __forceinline__ void ldm4(uint32_t* r, uint32_t addr) {
    asm volatile("ldmatrix.sync.aligned.m8n8.x4.shared.b16 {%0,%1,%2,%3}, [%4];"
        : "=r"(r[0]), "=r"(r[1]), "=r"(r[2]), "=r"(r[3]) : "r"(addr));
}
__device__ __forceinline__ void mma16816(float* d, const uint32_t* a, const uint32_t* b) {
    asm volatile(
        "mma.sync.aligned.m16n8k16.row.col.f32.bf16.bf16.f32 "
        "{%0,%1,%2,%3}, {%4,%5,%6,%7}, {%8,%9}, {%0,%1,%2,%3};"
        : "+f"(d[0]), "+f"(d[1]), "+f"(d[2]), "+f"(d[3])
        : "r"(a[0]), "r"(a[1]), "r"(a[2]), "r"(a[3]), "r"(b[0]), "r"(b[1]));
}
// pack two fp32 -> bf16x2 (low16 = a, high16 = b)
__device__ __forceinline__ uint32_t cvt_bf2(float a, float b) {
    uint32_t r;
    asm("cvt.rn.satfinite.bf16x2.f32 %0, %1, %2;" : "=r"(r) : "f"(b), "f"(a));
    return r;
}

// ---------------- threefry (verified R12) ----------------
__device__ __forceinline__ uint32_t rotl32(uint32_t x, int r) { return (x << r) | (x >> (32 - r)); }

__global__ void k_scalar(const float* __restrict__ ssp, const float* __restrict__ sep) {
    int p = threadIdx.x;
    if (p >= PPTS) return;
    const uint32_t k0 = 0u, k1 = 42u;
    const uint32_t kx = k0 ^ k1 ^ 0x1BD11BDAu;
    uint32_t ks[3] = {k0, k1, kx};
    uint32_t x0 = 0u + k0;
    uint32_t x1 = (uint32_t)p + k1;
    const int RA[4] = {13, 15, 26, 6};
    const int RB[4] = {17, 29, 16, 24};
    #pragma unroll
    for (int g = 0; g < 5; g++) {
        #pragma unroll
        for (int j = 0; j < 4; j++) {
            int r = (g & 1) ? RB[j] : RA[j];
            x0 += x1; x1 = rotl32(x1, r); x1 ^= x0;
        }
        x0 += ks[(g + 1) % 3];
        x1 += ks[(g + 2) % 3] + (uint32_t)(g + 1);
    }
    uint32_t bits = x0 ^ x1;
    float sstart = *ssp, send = *sep;
    float step = (send - sstart) / (float)(PPTS - 1);
    float u = __uint_as_float((bits >> 9) | 0x3F800000u) - 1.0f;
    u = fmaxf(0.0f, u);
    g_scalar[p] = (sstart + (float)p * step) + (u * (send - sstart)) / (float)(PPTS - 1);
}

// ---------------- positional encoding, sample-major ----------------
__global__ void k_feat(const float* __restrict__ ro, const float* __restrict__ rd) {
    int t = blockIdx.x * blockDim.x + threadIdx.x;
    if (t >= NSAMP) return;
    int b = t >> 7, p = t & 127;
    float s = g_scalar[p];
    float dx = rd[b * 3 + 0], dy = rd[b * 3 + 1], dz = rd[b * 3 + 2];
    float px = dx * s + ro[b * 3 + 0];
    float py = dy * s + ro[b * 3 + 1];
    float pz = dz * s + ro[b * 3 + 2];
    float* X = g_X + (size_t)t * INF;
    X[0] = px; X[1] = py; X[2] = pz;
    float freq = 3.14159265358979323846f;
    #pragma unroll
    for (int l = 0; l < LFREQ; l++) {
        float cx, sx, cy, sy, cz, sz;
        sincosf(px * freq, &sx, &cx);
        sincosf(py * freq, &sy, &cy);
        sincosf(pz * freq, &sz, &cz);
        float* q = X + 3 + l * 6;
        q[0] = cx; q[1] = cy; q[2] = cz; q[3] = sx; q[4] = sy; q[5] = sz;
        freq *= 2.0f;
    }
    X[63] = dx; X[64] = dy; X[65] = dz;
}

// ---------------- weight transpose + bf16 split (once per launch) ----------------
__global__ void k_prep(const float* __restrict__ W1, const float* __restrict__ W2) {
    int n = blockIdx.x;
    int tid = threadIdx.x;
    for (int e = tid; e < HID * KPAD; e += 256) {
        int h = e >> 7, k = e & 127;
        float v = (k < INF) ? W1[(size_t)n * INF * HID + (size_t)k * HID + h] : 0.0f;
        __nv_bfloat16 hi = __float2bfloat16(v);
        g_B1hi[n][e] = hi;
        g_B1lo[n][e] = __float2bfloat16(v - __bfloat162float(hi));
    }
    for (int e = tid; e < HID * KPAD; e += 256) {
        int h = e >> 7, k = e & 127;
        float v = W2[(size_t)n * HID * HID + (size_t)k * HID + h];
        __nv_bfloat16 hi = __float2bfloat16(v);
        g_B2hi[n][e] = hi;
        g_B2lo[n][e] = __float2bfloat16(v - __bfloat162float(hi));
    }
}

// ---------------- fused MLP via mma.sync bf16 split-precision ----------------
#define SR     136                 // bf16 row stride (272 B) for mma buffers
#define SA_HI  0
#define SA_LO  34816
#define SB_HI  69632
#define SB_LO  104448
#define SC_B1  139264
#define SC_B2  139776
#define SC_W3  140288
#define SC_B3  142336
#define SMEM_MLP 142352
// h2 fp32 [128][132] overlays SB_HI..(needs 67584 <= 69632)

__global__ void __launch_bounds__(512)
k_mlp(const float* __restrict__ b1, const float* __restrict__ b2,
      const float* __restrict__ W3, const float* __restrict__ b3) {
    extern __shared__ char sm[];
    uint32_t sb = smem_u32(sm);
    const int tid = threadIdx.x, w = tid >> 5, lane = tid & 31;
    const int tile = blockIdx.x, n = blockIdx.y, t0 = tile * 128;
    const int m0 = (w & 7) * 16, c0 = (w >> 3) * 64;
    const int g = lane >> 2, tg = lane & 3;

    // stage A = X split (rows [s][f], K1PAD=80, zero-pad f>=66)
    for (int e = tid; e < 128 * K1PAD; e += 512) {
        int s = e / K1PAD, f = e - s * K1PAD;
        float v = (f < INF) ? g_X[(size_t)(t0 + s) * INF + f] : 0.0f;
        __nv_bfloat16 hi = __float2bfloat16(v);
        ((__nv_bfloat16*)(sm + SA_HI))[s * SR + f] = hi;
        ((__nv_bfloat16*)(sm + SA_LO))[s * SR + f] = __float2bfloat16(v - __bfloat162float(hi));
    }
    // stage B1 hi/lo (64 u32 per row)
    {
        const uint32_t* sh = (const uint32_t*)g_B1hi[n];
        const uint32_t* sl = (const uint32_t*)g_B1lo[n];
        for (int e = tid; e < 128 * 64; e += 512) {
            int h = e >> 6, kk = e & 63;
            ((uint32_t*)(sm + SB_HI))[h * 68 + kk] = sh[e];
            ((uint32_t*)(sm + SB_LO))[h * 68 + kk] = sl[e];
        }
    }
    if (tid < 128) {
        ((float*)(sm + SC_B1))[tid] = b1[n * 128 + tid];
        ((float*)(sm + SC_B2))[tid] = b2[n * 128 + tid];
    }
    for (int e = tid; e < 512; e += 512) ((float*)(sm + SC_W3))[e] = W3[(size_t)n * 512 + e];
    if (tid < 4) ((float*)(sm + SC_B3))[tid] = b3[n * 4 + tid];
    __syncthreads();

    float acc[8][4];
    #pragma unroll
    for (int j = 0; j < 8; j++)
        #pragma unroll
        for (int q = 0; q < 4; q++) acc[j][q] = 0.0f;

    // ldmatrix address patterns
    const int arow = m0 + (lane < 16 ? lane : lane - 16);
    const int akof = (lane < 16) ? 0 : 8;
    const int brof = (lane & 7) + ((lane >= 16) ? 8 : 0);
    const int bkof = (lane & 8) ? 8 : 0;

    // ---- GEMM1: K=80 (5 ksteps), 3-pass split ----
    for (int kt = 0; kt < 5; kt++) {
        int k0 = kt * 16;
        uint32_t ah[4], al[4];
        uint32_t aaddr = sb + SA_HI + (uint32_t)(arow * SR + k0 + akof) * 2;
        ldm4(ah, aaddr);
        ldm4(al, aaddr + (SA_LO - SA_HI));
        #pragma unroll
        for (int pj = 0; pj < 4; pj++) {
            int n0 = c0 + pj * 16;
            uint32_t baddr = sb + SB_HI + (uint32_t)((n0 + brof) * SR + k0 + bkof) * 2;
            uint32_t bh[4], bl[4];
            ldm4(bh, baddr);
            ldm4(bl, baddr + (SB_LO - SB_HI));
            mma16816(acc[2 * pj],     ah, bh + 0);
            mma16816(acc[2 * pj + 1], ah, bh + 2);
            mma16816(acc[2 * pj],     ah, bl + 0);
            mma16816(acc[2 * pj + 1], ah, bl + 2);
            mma16816(acc[2 * pj],     al, bh + 0);
            mma16816(acc[2 * pj + 1], al, bh + 2);
        }
    }
    __syncthreads();   // all GEMM1 reads of SA/SB done

    // ---- epilogue1: relu(acc+b1) -> re-split into SA ----
    {
        const float* B = (const float*)(sm + SC_B1);
        #pragma unroll
        for (int j = 0; j < 8; j++) {
            int cb = c0 + 8 * j + 2 * tg;
            float b0v = B[cb], b1v = B[cb + 1];
            float v0 = fmaxf(acc[j][0] + b0v, 0.f), v1 = fmaxf(acc[j][1] + b1v, 0.f);
            float v2 = fmaxf(acc[j][2] + b0v, 0.f), v3 = fmaxf(acc[j][3] + b1v, 0.f);
            uint32_t h01 = cvt_bf2(v0, v1);
            float e0 = __uint_as_float(h01 << 16), e1 = __uint_as_float(h01 & 0xFFFF0000u);
            uint32_t l01 = cvt_bf2(v0 - e0, v1 - e1);
            uint32_t h23 = cvt_bf2(v2, v3);
            float e2 = __uint_as_float(h23 << 16), e3 = __uint_as_float(h23 & 0xFFFF0000u);
            uint32_t l23 = cvt_bf2(v2 - e2, v3 - e3);
            int o1 = ((m0 + g) * SR + cb) >> 1;
            int o2 = ((m0 + 8 + g) * SR + cb) >> 1;
            ((uint32_t*)(sm + SA_HI))[o1] = h01; ((uint32_t*)(sm + SA_LO))[o1] = l01;
            ((uint32_t*)(sm + SA_HI))[o2] = h23; ((uint32_t*)(sm + SA_LO))[o2] = l23;
        }
    }
    // stage B2 over B1
    {
        const uint32_t* sh = (const uint32_t*)g_B2hi[n];
        const uint32_t* sl = (const uint32_t*)g_B2lo[n];
        for (int e = tid; e < 128 * 64; e += 512) {
            int h = e >> 6, kk = e & 63;
            ((uint32_t*)(sm + SB_HI))[h * 68 + kk] = sh[e];
            ((uint32_t*)(sm + SB_LO))[h * 68 + kk] = sl[e];
        }
    }
    __syncthreads();

    // ---- GEMM2: K=128 (8 ksteps) ----
    #pragma unroll
    for (int j = 0; j < 8; j++)
        #pragma unroll
        for (int q = 0; q < 4; q++) acc[j][q] = 0.0f;
    for (int kt = 0; kt < 8; kt++) {
        int k0 = kt * 16;
        uint32_t ah[4], al[4];
        uint32_t aaddr = sb + SA_HI + (uint32_t)(arow * SR + k0 + akof) * 2;
        ldm4(ah, aaddr);
        ldm4(al, aaddr + (SA_LO - SA_HI));
        #pragma unroll
        for (int pj = 0; pj < 4; pj++) {
            int n0 = c0 + pj * 16;
            uint32_t baddr = sb + SB_HI + (uint32_t)((n0 + brof) * SR + k0 + bkof) * 2;
            uint32_t bh[4], bl[4];
            ldm4(bh, baddr);
            ldm4(bl, baddr + (SB_LO - SB_HI));
            mma16816(acc[2 * pj],     ah, bh + 0);
            mma16816(acc[2 * pj + 1], ah, bh + 2);
            mma16816(acc[2 * pj],     ah, bl + 0);
            mma16816(acc[2 * pj + 1], ah, bl + 2);
            mma16816(acc[2 * pj],     al, bh + 0);
            mma16816(acc[2 * pj + 1], al, bh + 2);
        }
    }
    __syncthreads();   // all GEMM2 reads done; SB region now free

    // ---- epilogue2: h2 = relu(acc+b2) fp32 -> overlay buffer [s][132] ----
    {
        const float* B = (const float*)(sm + SC_B2);
        float* H2 = (float*)(sm + SB_HI);
        #pragma unroll
        for (int j = 0; j < 8; j++) {
            int cb = c0 + 8 * j + 2 * tg;
            float b0v = B[cb], b1v = B[cb + 1];
            float2 pA, pB;
            pA.x = fmaxf(acc[j][0] + b0v, 0.f);
            pA.y = fmaxf(acc[j][1] + b1v, 0.f);
            pB.x = fmaxf(acc[j][2] + b0v, 0.f);
            pB.y = fmaxf(acc[j][3] + b1v, 0.f);
            *(float2*)&H2[(m0 + g) * 132 + cb]     = pA;
            *(float2*)&H2[(m0 + 8 + g) * 132 + cb] = pB;
        }
    }
    __syncthreads();

    // ---- layer3: exact fp32, 512 threads = 128 s x 4 o ----
    {
        int o = tid >> 7, s = tid & 127;
        const float* W3s = (const float*)(sm + SC_W3);
        const float* H2 = (const float*)(sm + SB_HI);
        float a = ((const float*)(sm + SC_B3))[o];
        #pragma unroll 4
        for (int k = 0; k < HID; k++)
            a += H2[s * 132 + k] * W3s[k * 4 + o];
        g_evals[((size_t)n * NSAMP + t0 + s) * 4 + o] = a;
    }
}

// ---------------- mixture + volume rendering + splits (unchanged) ----------------
__global__ void __launch_bounds__(128)
k_render(const float* __restrict__ ro, const float* __restrict__ rd,
         const float* __restrict__ Ws, const float* __restrict__ bs,
         float* __restrict__ out) {
    int b = blockIdx.x;
    int p = threadIdx.x;
    int t = b * PPTS + p;

    float dx = rd[b * 3 + 0], dy = rd[b * 3 + 1], dz = rd[b * 3 + 2];
    float s  = g_scalar[p];
    float px = dx * s + ro[b * 3 + 0];
    float py = dy * s + ro[b * 3 + 1];
    float pz = dz * s + ro[b * 3 + 2];

    float lo_[NNET];
    float m = -1e30f;
    #pragma unroll
    for (int n = 0; n < NNET; n++) {
        float l = px * Ws[0 * NNET + n] + py * Ws[1 * NNET + n] + pz * Ws[2 * NNET + n] + bs[n];
        lo_[n] = l;
        m = fmaxf(m, l);
    }
    float denom = 0.0f;
    #pragma unroll
    for (int n = 0; n < NNET; n++) { lo_[n] = expf(lo_[n] - m); denom += lo_[n]; }
    float inv = 1.0f / denom;
    float* spl = out + BATCH * 3;
    float nv0 = 0.f, nv1 = 0.f, nv2 = 0.f, nv3 = 0.f;
    #pragma unroll
    for (int n = 0; n < NNET; n++) {
        float spn = lo_[n] * inv;
        spl[(size_t)t * NNET + n] = spn;
        float4 ev = *(const float4*)&g_evals[((size_t)n * NSAMP + t) * 4];
        nv0 += spn * ev.x;
        nv1 += spn * ev.y;
        nv2 += spn * ev.z;
        nv3 += spn * ev.w;
    }

    float sdv = 0.0f;
    if (p < PPTS - 1) sdv = nv3 * (g_scalar[p + 1] - g_scalar[p]);

    __shared__ float sc[PPTS];
    sc[p] = sdv;
    __syncthreads();
    #pragma unroll
    for (int off = 1; off < PPTS; off <<= 1) {
        float add = (p >= off) ? sc[p - off] : 0.0f;
        __syncthreads();
        sc[p] += add;
        __syncthreads();
    }
    float csum = sc[p];
    float w = (p < PPTS - 1) ? expf(csum) * (1.0f - expf(-sdv)) : 0.0f;

    float rc[3] = {w * nv0, w * nv1, w * nv2};
    #pragma unroll
    for (int c = 0; c < 3; c++) {
        __syncthreads();
        sc[p] = rc[c];
        __syncthreads();
        for (int off = 64; off > 0; off >>= 1) {
            if (p < off) sc[p] += sc[p + off];
            __syncthreads();
        }
        if (p == 0) out[b * 3 + c] = sc[0];
    }
}

// ---------------- launch ----------------
extern "C" void kernel_launch(void* const* d_in, const int* in_sizes, int n_in,
                              void* d_out, int out_size) {
    fprintf(stderr, "[kdiag] n_in=%d out_size=%d sizes:", n_in, out_size);
    for (int i = 0; i < n_in; i++) fprintf(stderr, " %d", in_sizes[i]);
    fprintf(stderr, "\n");

    const float* ro = (const float*)d_in[0];
    const float* rd = (const float*)d_in[1];
    const float* ss = (const float*)d_in[2];
    const float* se = (const float*)d_in[3];

    int iW1 = -1;
    for (int i = 0; i < n_in; i++) {
        if (in_sizes[i] == NNET * INF * HID) { iW1 = i; break; }
    }
    if (iW1 < 0) iW1 = 5;
    const float* W1 = (const float*)d_in[iW1 + 0];
    const float* b1 = (const float*)d_in[iW1 + 1];
    const float* W2 = (const float*)d_in[iW1 + 2];
    const float* b2 = (const float*)d_in[iW1 + 3];
    const float* W3 = (const float*)d_in[iW1 + 4];
    const float* b3 = (const float*)d_in[iW1 + 5];
    const float* Ws = (const float*)d_in[iW1 + 6];
    const float* bs = (const float*)d_in[iW1 + 7];
    float* out = (float*)d_out;

    cudaFuncSetAttribute(k_mlp, cudaFuncAttributeMaxDynamicSharedMemorySize, SMEM_MLP);

    k_scalar<<<1, PPTS>>>(ss, se);
    k_prep<<<NNET, 256>>>(W1, W2);
    k_feat<<<NSAMP / 256, 256>>>(ro, rd);
    k_mlp<<<dim3(BATCH, NNET), 512, SMEM_MLP>>>(b1, b2, W3, b3);
    k_render<<<BATCH, PPTS>>>(ro, rd, Ws, bs, out);
}